// round 14
// baseline (speedup 1.0000x reference)
#include <cuda_runtime.h>
#include <cuda_bf16.h>
#include <math_constants.h>
#include <cstdint>

#define BATCH 8
#define CH 128
#define NT 4096
#define NF 2049
#define MROWS (BATCH * NF)   // 16392
#define LOGN 12
#define SQRTN 64.0f
#define FP 2176              // padded F: 17*128 = 34*64
#define NEG_INF __int_as_float(0xff800000)
#define SCALE 0.08838834764831845f   // 1/sqrt(128)

// ---------------- scratch (device globals; no allocation allowed) ----------------
__device__ float2 g_X[(size_t)MROWS * CH];    // x_fft   (B,F,C)
__device__ float2 g_Kp[(size_t)MROWS * CH];   // K       (B,F,C)
__device__ float2 g_Vp[(size_t)MROWS * CH];   // V       (B,F,C)
__device__ float2 g_ctx[(size_t)MROWS * CH];  // context (B,F,C)
__device__ float  g_energy[MROWS];
__device__ float  g_norm[MROWS];
__device__ float  g_med[BATCH];
__device__ float  g_qv[2];
__device__ float  g_thr[1];
__device__ float2 g_TW[NT / 2];               // exp(-2*pi*i*k/N)
__device__ float  g_WT[2 * CH * CH];          // W_K^T then W_V^T
__device__ unsigned g_hist[65536];
__device__ int    g_bk[2];

// GEMM staging (fp32 values PRE-ROUNDED to tf32 precision by producers)
__device__ __align__(16) float g_Qf [(size_t)BATCH * FP * 256];  // scale*[Qr|Qi]
__device__ __align__(16) float g_Krf[(size_t)BATCH * FP * 256];  // [Kr|-Ki]
__device__ __align__(16) float g_Kif[(size_t)BATCH * FP * 256];  // [Ki|Kr]
__device__ __align__(16) float g_Vf [(size_t)BATCH * FP * 256];  // [Vr|Vi]
__device__ __align__(16) float g_VfT[(size_t)BATCH * 256 * FP];  // V transposed (n-major)
__device__ __align__(16) float g_ctxr[(size_t)BATCH * FP * 256]; // [ctx_r|ctx_i]

// ---------------- helpers ----------------
__device__ __forceinline__ float tf32r(float x) {
    uint32_t u;
    asm("cvt.rna.tf32.f32 %0, %1;" : "=r"(u) : "f"(x));
    return __uint_as_float(u);
}

__device__ __forceinline__ void mma_tf32(float* c,
    float a0, float a1, float a2, float a3, float b0, float b1) {
    asm volatile(
        "mma.sync.aligned.m16n8k8.row.col.f32.tf32.tf32.f32 "
        "{%0,%1,%2,%3},{%4,%5,%6,%7},{%8,%9},{%0,%1,%2,%3};\n"
        : "+f"(c[0]), "+f"(c[1]), "+f"(c[2]), "+f"(c[3])
        : "r"(__float_as_uint(a0)), "r"(__float_as_uint(a1)),
          "r"(__float_as_uint(a2)), "r"(__float_as_uint(a3)),
          "r"(__float_as_uint(b0)), "r"(__float_as_uint(b1)));
}

__device__ __forceinline__ void cp16(uint32_t saddr, const void* gptr) {
    asm volatile("cp.async.cg.shared.global [%0], [%1], 16;\n"
                 :: "r"(saddr), "l"(gptr));
}
__device__ __forceinline__ void cp_commit() {
    asm volatile("cp.async.commit_group;\n");
}
template <int N>
__device__ __forceinline__ void cp_wait() {
    asm volatile("cp.async.wait_group %0;\n" :: "n"(N));
}

// ---------------- init: twiddles + transposed weights ----------------
__global__ void k_init(const float* __restrict__ WK, const float* __restrict__ WV) {
    int i = blockIdx.x * blockDim.x + threadIdx.x;
    if (i < NT / 2) {
        float s, c;
        sincospif(2.0f * (float)i / (float)NT, &s, &c);
        g_TW[i] = make_float2(c, -s);
    }
    if (i < CH * CH) {
        int cc = i >> 7, cp = i & 127;
        g_WT[cc * CH + cp] = WK[cp * CH + cc];
        g_WT[CH * CH + cc * CH + cp] = WV[cp * CH + cc];
    }
}

// ---------------- shared-memory radix-2 FFT ----------------
template <bool INV>
__device__ __forceinline__ void fft4096(float2* sh, int tid, int nthreads) {
    #pragma unroll 1
    for (int s = 1; s <= LOGN; s++) {
        int mh = 1 << (s - 1);
        for (int k = tid; k < NT / 2; k += nthreads) {
            int j = k & (mh - 1);
            int base = ((k - j) << 1) + j;
            float2 w = g_TW[j << (LOGN - s)];
            if (INV) w.y = -w.y;
            float2 a = sh[base];
            float2 bb = sh[base + mh];
            float tr = w.x * bb.x - w.y * bb.y;
            float ti = w.x * bb.y + w.y * bb.x;
            sh[base]      = make_float2(a.x + tr, a.y + ti);
            sh[base + mh] = make_float2(a.x - tr, a.y - ti);
        }
        __syncthreads();
    }
}

__global__ void k_rfft(const float* __restrict__ x) {
    __shared__ float2 sh[NT];
    int row = blockIdx.x;
    int b = row >> 7, c = row & 127;
    const float* xp = x + (size_t)row * NT;
    for (int n = threadIdx.x; n < NT; n += blockDim.x)
        sh[__brev(n) >> (32 - LOGN)] = make_float2(xp[n], 0.f);
    __syncthreads();
    fft4096<false>(sh, threadIdx.x, blockDim.x);
    const float inv = 1.0f / SQRTN;
    for (int f = threadIdx.x; f < NF; f += blockDim.x) {
        float2 v = sh[f];
        g_X[((size_t)b * NF + f) * CH + c] = make_float2(v.x * inv, v.y * inv);
    }
}

// ---------------- K/V projection ----------------
__global__ void k_proj(const float* __restrict__ bK, const float* __restrict__ bV) {
    __shared__ float2 xs[16 * CH];
    int r0 = blockIdx.x * 16;
    int tid = threadIdx.x;
    for (int idx = tid; idx < 16 * CH; idx += 256) {
        int r = idx >> 7, c = idx & 127;
        int gr = r0 + r;
        xs[idx] = (gr < MROWS) ? g_X[(size_t)gr * CH + c] : make_float2(0.f, 0.f);
    }
    __syncthreads();
    int cp = tid & 127;
    int half = tid >> 7;
    float kr[8] = {0}, ki[8] = {0}, vr[8] = {0}, vi[8] = {0};
    const float* wk = g_WT;
    const float* wv = g_WT + CH * CH;
    for (int c = 0; c < CH; c++) {
        float a = __ldg(wk + c * CH + cp);
        float bb = __ldg(wv + c * CH + cp);
        #pragma unroll
        for (int r = 0; r < 8; r++) {
            float2 xv = xs[(half * 8 + r) * CH + c];
            kr[r] += xv.x * a;  ki[r] += xv.y * a;
            vr[r] += xv.x * bb; vi[r] += xv.y * bb;
        }
    }
    #pragma unroll
    for (int r = 0; r < 8; r++) {
        int gr = r0 + half * 8 + r;
        if (gr < MROWS) {
            if (gr % NF == 0) { kr[r] += SQRTN * bK[cp]; vr[r] += SQRTN * bV[cp]; }
            g_Kp[(size_t)gr * CH + cp] = make_float2(kr[r], ki[r]);
            g_Vp[(size_t)gr * CH + cp] = make_float2(vr[r], vi[r]);
        }
    }
}

// ---------------- pack staging buffers (tf32-pre-rounded fp32; coalesced) ----------------
__global__ void k_pack() {
    int f = blockIdx.x, b = blockIdx.y, n = threadIdx.x;   // n in [0,256)
    size_t o = ((size_t)b * FP + f) * 256 + n;
    float q = 0.f, kr = 0.f, ki = 0.f, vv = 0.f;
    if (f < NF) {
        int c = n & 127;
        size_t src = ((size_t)b * NF + f) * CH + c;
        float2 X = g_X[src], K = g_Kp[src], V = g_Vp[src];
        if (n < 128) { q = X.x; kr = K.x;  ki = K.y; vv = V.x; }
        else         { q = X.y; kr = -K.y; ki = K.x; vv = V.y; }
    }
    g_Qf[o]  = tf32r(q * SCALE);
    g_Krf[o] = tf32r(kr);
    g_Kif[o] = tf32r(ki);
    g_Vf[o]  = tf32r(vv);
}

// ---------------- tiled transpose of V: g_Vf (FPx256) -> g_VfT (256xFP) ----------------
__global__ void k_vt() {
    __shared__ float t[32][33];
    int b = blockIdx.z;
    int f0 = blockIdx.x * 32, n0 = blockIdx.y * 32;
    int x = threadIdx.x, y = threadIdx.y;    // block (32, 8)
    #pragma unroll
    for (int i = 0; i < 32; i += 8)
        t[y + i][x] = g_Vf[((size_t)b * FP + f0 + y + i) * 256 + n0 + x];
    __syncthreads();
    #pragma unroll
    for (int i = 0; i < 32; i += 8)
        g_VfT[((size_t)b * 256 + n0 + y + i) * FP + f0 + x] = t[x][y + i];
}

// ---------------- energy / median / quantile ----------------
__global__ void k_energy() {
    int row = blockIdx.x;
    int c = threadIdx.x;
    float2 v = g_X[(size_t)row * CH + c];
    float e = v.x * v.x + v.y * v.y;
    #pragma unroll
    for (int o = 16; o; o >>= 1) e += __shfl_xor_sync(~0u, e, o);
    __shared__ float ws[4];
    if ((c & 31) == 0) ws[c >> 5] = e;
    __syncthreads();
    if (c == 0) g_energy[row] = ws[0] + ws[1] + ws[2] + ws[3];
}

__global__ void k_median() {
    int i = blockIdx.x * blockDim.x + threadIdx.x;
    if (i >= MROWS) return;
    int b = i / NF;
    float e = g_energy[i];
    const float* eb = g_energy + b * NF;
    int less = 0, leq = 0;
    for (int f = 0; f < NF; f++) {
        float v = __ldg(eb + f);
        less += (v < e);
        leq  += (v <= e);
    }
    if (less <= (NF / 2) && (NF / 2) < leq) g_med[b] = e;
}

__global__ void k_norm() {
    int i = blockIdx.x * blockDim.x + threadIdx.x;
    if (i < MROWS) g_norm[i] = g_energy[i] / (g_med[i / NF] + 1e-6f);
}

// histogram over top-16 bits of the (non-negative) float bit pattern: monotonic buckets
__global__ void k_hzero() {
    int i = blockIdx.x * blockDim.x + threadIdx.x;
    if (i < 65536) g_hist[i] = 0;
}
__global__ void k_hist() {
    int i = blockIdx.x * blockDim.x + threadIdx.x;
    if (i < MROWS) atomicAdd(&g_hist[__float_as_uint(g_norm[i]) >> 16], 1u);
}
__global__ void k_hscan(const float* __restrict__ thp) {
    __shared__ unsigned ps[1024];
    int t = threadIdx.x;
    unsigned s = 0;
    #pragma unroll 4
    for (int j = 0; j < 64; j++) s += g_hist[t * 64 + j];
    ps[t] = s;
    __syncthreads();
    for (int off = 1; off < 1024; off <<= 1) {
        unsigned v = (t >= off) ? ps[t - off] : 0;
        __syncthreads();
        ps[t] += v;
        __syncthreads();
    }
    unsigned run = (t == 0) ? 0u : ps[t - 1];
    float q = thp[0];
    int k0 = (int)floorf(q * (float)(MROWS - 1));
    unsigned r0 = (unsigned)k0, r1 = (unsigned)(k0 + 1);
    for (int j = 0; j < 64; j++) {
        unsigned c = g_hist[t * 64 + j];
        if (r0 >= run && r0 < run + c) g_bk[0] = t * 64 + j;
        if (r1 >= run && r1 < run + c) g_bk[1] = t * 64 + j;
        run += c;
    }
}
__global__ void k_qsel(const float* __restrict__ thp) {
    int i = blockIdx.x * blockDim.x + threadIdx.x;
    if (i >= MROWS) return;
    float v = g_norm[i];
    int bb = (int)(__float_as_uint(v) >> 16);
    int bk0 = g_bk[0], bk1 = g_bk[1];
    if (bb != bk0 && bb != bk1) return;
    float q = thp[0];
    int k = (int)floorf(q * (float)(MROWS - 1));
    int less = 0, leq = 0;
    for (int j = 0; j < MROWS; j++) {
        float u = __ldg(g_norm + j);
        less += (u < v);
        leq  += (u <= v);
    }
    if (less <= k && k < leq)         g_qv[0] = v;
    if (less <= k + 1 && k + 1 < leq) g_qv[1] = v;
}

__global__ void k_thr(const float* __restrict__ thp) {
    float q = thp[0];
    float h = q * (float)(MROWS - 1);
    float k = floorf(h);
    g_thr[0] = g_qv[0] + (h - k) * (g_qv[1] - g_qv[0]);
}

// ---------------- fused flash attention: scores + online softmax + PV ----------------
// Block: 64 query rows, 256 threads (8 warps as 2x4).
// Q tile (64x256) persistent in smem; 33 key tiles of 64.
#define FL_SMEM (50816 * 4)
__global__ void __launch_bounds__(256) k_flash() {
    extern __shared__ __align__(16) float dsm[];
    float* Qs   = dsm;
    float* Krs  = dsm + 16640;
    float* Kis  = dsm + 23552;
    float* Vs   = dsm + 30464;
    float* Ps   = dsm + 45824;
    float* m_s  = dsm + 50176;
    float* l_s  = dsm + 50240;
    float* pmax = dsm + 50304;
    float* psum = dsm + 50560;

    int b = blockIdx.y, row0 = blockIdx.x * 64;
    int tid = threadIdx.x, w = tid >> 5, lane = tid & 31;
    int g = lane >> 2, t = lane & 3;
    int wr  = (w & 1) * 32;
    int wcS = (w >> 1) * 16;
    int wcO = (w >> 1) * 64;

    const float* Qb  = g_Qf  + ((size_t)b * FP + row0) * 256;
    const float* Vtb = g_VfT + (size_t)b * 256 * FP;

    uint32_t aQ  = (uint32_t)__cvta_generic_to_shared(Qs);
    uint32_t aKr = (uint32_t)__cvta_generic_to_shared(Krs);
    uint32_t aKi = (uint32_t)__cvta_generic_to_shared(Kis);
    uint32_t aV  = (uint32_t)__cvta_generic_to_shared(Vs);

    // prologue: FULL Q tile load (64 rows x 256 floats = 4096 cp16, 16/thread)
    {
        int row = tid >> 2, q4 = tid & 3;
        #pragma unroll
        for (int i = 0; i < 16; i++) {
            int c16 = q4 + i * 4;                    // 0..63 -> floats 0..255
            cp16(aQ + (uint32_t)(row * 260 + c16 * 4) * 4,
                 Qb + (size_t)row * 256 + c16 * 4);
        }
        cp_commit();
    }
    if (tid < 64) { m_s[tid] = NEG_INF; l_s[tid] = 0.f; }

    float acc[2][8][4];
    #pragma unroll
    for (int rt = 0; rt < 2; rt++)
        #pragma unroll
        for (int nt = 0; nt < 8; nt++)
            #pragma unroll
            for (int e = 0; e < 4; e++) acc[rt][nt][e] = 0.f;

    const int NTILES = 33;
    for (int tile = 0; tile < NTILES; tile++) {
        int gk0 = tile * 64;
        const float* Krb = g_Krf + ((size_t)b * FP + gk0) * 256;
        const float* Kib = g_Kif + ((size_t)b * FP + gk0) * 256;

        auto issue_k = [&](int kt) {
            int s = kt % 3;
            #pragma unroll
            for (int j = 0; j < 2; j++) {
                int idx = tid * 2 + j;
                int row = idx >> 3, c16 = idx & 7;
                cp16(aKr + (uint32_t)(s * 2304 + row * 36 + c16 * 4) * 4,
                     Krb + (size_t)row * 256 + kt * 32 + c16 * 4);
                cp16(aKi + (uint32_t)(s * 2304 + row * 36 + c16 * 4) * 4,
                     Kib + (size_t)row * 256 + kt * 32 + c16 * 4);
            }
            cp_commit();
        };
        auto issue_v = [&](int vt) {
            int s = vt % 3;
            #pragma unroll
            for (int j = 0; j < 4; j++) {
                int idx = tid * 4 + j;
                int n = idx >> 2, c16 = idx & 3;
                cp16(aV + (uint32_t)(s * 5120 + n * 20 + c16 * 4) * 4,
                     Vtb + (size_t)n * FP + gk0 + vt * 16 + c16 * 4);
            }
            cp_commit();
        };

        // ---- S phase ----
        float sr[2][2][4], si[2][2][4];
        #pragma unroll
        for (int rt = 0; rt < 2; rt++)
            #pragma unroll
            for (int nt = 0; nt < 2; nt++)
                #pragma unroll
                for (int e = 0; e < 4; e++) { sr[rt][nt][e] = 0.f; si[rt][nt][e] = 0.f; }

        issue_k(0); issue_k(1);
        for (int kt = 0; kt < 8; kt++) {
            if (kt == 7) cp_wait<0>(); else cp_wait<1>();
            __syncthreads();
            if (kt + 2 < 8) issue_k(kt + 2);
            const float* Krc = Krs + (kt % 3) * 2304;
            const float* Kic = Kis + (kt % 3) * 2304;
            #pragma unroll
            for (int k8 = 0; k8 < 32; k8 += 8) {
                float a0[2], a1[2], a2[2], a3[2];
                #pragma unroll
                for (int rt = 0; rt < 2; rt++) {
                    const float* qr = Qs + (wr + rt * 16 + g) * 260 + kt * 32 + k8 + t;
                    a0[rt] = qr[0];       a2[rt] = qr[4];
                    a1[rt] = qr[8 * 260]; a3[rt] = qr[8 * 260 + 4];
                }
                #pragma unroll
                for (int nt = 0; nt < 2; nt++) {
                    int n = wcS + nt * 8 + g;
                    float br0 = Krc[n * 36 + k8 + t], br1 = Krc[n * 36 + k8 + t + 4];
                    float bi0 = Kic[n * 36 + k8 + t], bi1 = Kic[n * 36 + k8 + t + 4];
                    #pragma unroll
                    for (int rt = 0; rt < 2; rt++) {
                        mma_tf32(sr[rt][nt], a0[rt], a1[rt], a2[rt], a3[rt], br0, br1);
                        mma_tf32(si[rt][nt], a0[rt], a1[rt], a2[rt], a3[rt], bi0, bi1);
                    }
                }
            }
        }
        issue_v(0); issue_v(1);

        // ---- online softmax ----
        float p[2][2][4];
        #pragma unroll
        for (int rt = 0; rt < 2; rt++)
            #pragma unroll
            for (int nt = 0; nt < 2; nt++)
                #pragma unroll
                for (int e = 0; e < 4; e++) {
                    float x = sr[rt][nt][e], y = si[rt][nt][e];
                    int kidx = gk0 + wcS + nt * 8 + t * 2 + (e & 1);
                    p[rt][nt][e] = (kidx < NF) ? sqrtf(x * x + y * y) : NEG_INF;
                }
        #pragma unroll
        for (int rt = 0; rt < 2; rt++)
            #pragma unroll
            for (int half = 0; half < 2; half++) {
                float rm = fmaxf(fmaxf(p[rt][0][half * 2], p[rt][0][half * 2 + 1]),
                                 fmaxf(p[rt][1][half * 2], p[rt][1][half * 2 + 1]));
                rm = fmaxf(rm, __shfl_xor_sync(~0u, rm, 1));
                rm = fmaxf(rm, __shfl_xor_sync(~0u, rm, 2));
                if (t == 0) pmax[(wr + rt * 16 + g + half * 8) * 4 + (w >> 1)] = rm;
            }
        __syncthreads();
        float corr[2][2], mnew[2][2];
        #pragma unroll
        for (int rt = 0; rt < 2; rt++)
            #pragma unroll
            for (int half = 0; half < 2; half++) {
                int r = wr + rt * 16 + g + half * 8;
                float tm = fmaxf(fmaxf(pmax[r * 4], pmax[r * 4 + 1]),
                                 fmaxf(pmax[r * 4 + 2], pmax[r * 4 + 3]));
                float mo = m_s[r];
                float mn = fmaxf(mo, tm);
                mnew[rt][half] = mn;
                corr[rt][half] = __expf(mo - mn);
            }
        #pragma unroll
        for (int rt = 0; rt < 2; rt++)
            #pragma unroll
            for (int half = 0; half < 2; half++) {
                int r = wr + rt * 16 + g + half * 8;
                float mn = mnew[rt][half];
                float s0 = 0.f;
                #pragma unroll
                for (int nt = 0; nt < 2; nt++) {
                    float e0 = __expf(p[rt][nt][half * 2 + 0] - mn);
                    float e1 = __expf(p[rt][nt][half * 2 + 1] - mn);
                    s0 += e0 + e1;
                    *(float2*)&Ps[r * 68 + wcS + nt * 8 + t * 2] =
                        make_float2(tf32r(e0), tf32r(e1));
                }
                s0 += __shfl_xor_sync(~0u, s0, 1);
                s0 += __shfl_xor_sync(~0u, s0, 2);
                if (t == 0) psum[r * 4 + (w >> 1)] = s0;
                float cc = corr[rt][half];
                #pragma unroll
                for (int nt = 0; nt < 8; nt++) {
                    acc[rt][nt][half * 2 + 0] *= cc;
                    acc[rt][nt][half * 2 + 1] *= cc;
                }
            }
        __syncthreads();
        if (tid < 64) {
            int r = tid;
            float tm = fmaxf(fmaxf(pmax[r * 4], pmax[r * 4 + 1]),
                             fmaxf(pmax[r * 4 + 2], pmax[r * 4 + 3]));
            float mo = m_s[r];
            float mn = fmaxf(mo, tm);
            l_s[r] = l_s[r] * __expf(mo - mn)
                   + psum[r * 4] + psum[r * 4 + 1] + psum[r * 4 + 2] + psum[r * 4 + 3];
            m_s[r] = mn;
        }

        // ---- V phase ----
        for (int vt = 0; vt < 4; vt++) {
            if (vt == 3) cp_wait<0>(); else cp_wait<1>();
            __syncthreads();
            if (vt + 2 < 4) issue_v(vt + 2);
            const float* Vc = Vs + (vt % 3) * 5120;
            #pragma unroll
            for (int k8 = 0; k8 < 16; k8 += 8) {
                float a0[2], a1[2], a2[2], a3[2];
                #pragma unroll
                for (int rt = 0; rt < 2; rt++) {
                    const float* pr = Ps + (wr + rt * 16 + g) * 68 + vt * 16 + k8 + t;
                    a0[rt] = pr[0];      a2[rt] = pr[4];
                    a1[rt] = pr[8 * 68]; a3[rt] = pr[8 * 68 + 4];
                }
                #pragma unroll
                for (int nt = 0; nt < 8; nt++) {
                    int n = wcO + nt * 8 + g;
                    float b0 = Vc[n * 20 + k8 + t], b1 = Vc[n * 20 + k8 + t + 4];
                    #pragma unroll
                    for (int rt = 0; rt < 2; rt++)
                        mma_tf32(acc[rt][nt], a0[rt], a1[rt], a2[rt], a3[rt], b0, b1);
                }
            }
        }
    }

    // ---- epilogue ----
    float* O = g_ctxr + ((size_t)b * FP + row0) * 256;
    #pragma unroll
    for (int rt = 0; rt < 2; rt++)
        #pragma unroll
        for (int half = 0; half < 2; half++) {
            int r = wr + rt * 16 + g + half * 8;
            float inv = 1.0f / l_s[r];
            #pragma unroll
            for (int nt = 0; nt < 8; nt++) {
                *(float2*)&O[(size_t)r * 256 + wcO + nt * 8 + t * 2] =
                    make_float2(acc[rt][nt][half * 2 + 0] * inv,
                                acc[rt][nt][half * 2 + 1] * inv);
            }
        }
}

// ---------------- combine: high-freq residual + pack into g_ctx ----------------
__global__ void k_combine(const float* __restrict__ whigh) {
    int f = blockIdx.x, b = blockIdx.y, c = threadIdx.x;   // c in [0,128)
    size_t ro = ((size_t)b * FP + f) * 256;
    float cr = g_ctxr[ro + c];
    float ci = g_ctxr[ro + 128 + c];
    if (g_norm[b * NF + f] > g_thr[0]) {
        float2 xv = g_X[((size_t)b * NF + f) * CH + c];
        float wrr = whigh[c * 2], wi = whigh[c * 2 + 1];
        cr += xv.x * wrr - xv.y * wi;
        ci += xv.x * wi + xv.y * wrr;
    }
    g_ctx[((size_t)b * NF + f) * CH + c] = make_float2(cr, ci);
}

// ---------------- irfft ----------------
__global__ void k_irfft(float* __restrict__ out) {
    __shared__ float2 sh[NT];
    int row = blockIdx.x;
    int b = row >> 7, c = row & 127;
    size_t base = ((size_t)b * NF) * CH + c;
    for (int n = threadIdx.x; n < NT; n += blockDim.x) {
        float2 v;
        if (n == 0)            { v = g_ctx[base]; v.y = 0.f; }
        else if (n < NT / 2)   { v = g_ctx[base + (size_t)n * CH]; }
        else if (n == NT / 2)  { v = g_ctx[base + (size_t)(NT / 2) * CH]; v.y = 0.f; }
        else                   { v = g_ctx[base + (size_t)(NT - n) * CH]; v.y = -v.y; }
        sh[__brev(n) >> (32 - LOGN)] = v;
    }
    __syncthreads();
    fft4096<true>(sh, threadIdx.x, blockDim.x);
    float* op = out + (size_t)row * NT;
    const float inv = 1.0f / SQRTN;
    for (int n = threadIdx.x; n < NT; n += blockDim.x)
        op[n] = sh[n].x * inv;
}

// ---------------- launch ----------------
extern "C" void kernel_launch(void* const* d_in, const int* in_sizes, int n_in,
                              void* d_out, int out_size) {
    const float* x   = (const float*)d_in[0];
    const float* WK  = (const float*)d_in[1];
    const float* bK  = (const float*)d_in[2];
    const float* WV  = (const float*)d_in[3];
    const float* bV  = (const float*)d_in[4];
    const float* wh  = (const float*)d_in[5];
    const float* thp = (const float*)d_in[6];
    float* out = (float*)d_out;

    cudaFuncSetAttribute(k_flash, cudaFuncAttributeMaxDynamicSharedMemorySize, FL_SMEM);

    k_init<<<64, 256>>>(WK, WV);
    k_rfft<<<BATCH * CH, 256>>>(x);
    k_proj<<<(MROWS + 15) / 16, 256>>>(bK, bV);
    k_pack<<<dim3(FP, BATCH), 256>>>();
    k_vt<<<dim3(FP / 32, 256 / 32, BATCH), dim3(32, 8)>>>();
    k_flash<<<dim3(33, BATCH), 256, FL_SMEM>>>();
    k_energy<<<MROWS, 128>>>();
    k_median<<<(MROWS + 255) / 256, 256>>>();
    k_norm<<<(MROWS + 255) / 256, 256>>>();
    k_hzero<<<256, 256>>>();
    k_hist<<<(MROWS + 255) / 256, 256>>>();
    k_hscan<<<1, 1024>>>(thp);
    k_qsel<<<(MROWS + 255) / 256, 256>>>(thp);
    k_thr<<<1, 1>>>(thp);
    k_combine<<<dim3(NF, BATCH), 128>>>(wh);
    k_irfft<<<BATCH * CH, 256>>>(out);
}